// round 2
// baseline (speedup 1.0000x reference)
#include <cuda_runtime.h>
#include <cuda_fp16.h>
#include <cstdint>

// ---------------- problem constants ----------------
constexpr int BATCH = 32768;
constexpr int KIN   = 256;      // 16*4*4 flattened input per sample
constexpr int NC    = 3648;     // real combined features
constexpr int NPAD  = 3712;     // padded to 29*128
constexpr int H1    = 512;
constexpr int H2    = 128;
constexpr int NA    = 4;

// ---------------- scratch (device globals; no allocation) ----------------
__device__ __align__(256) __half g_Xh  [(size_t)BATCH * KIN];
__device__ __align__(256) __half g_Wbig[(size_t)NPAD * KIN];
__device__ __align__(256) float  g_bbig[NPAD];
__device__ __align__(256) __half g_comb[(size_t)BATCH * NPAD];   // ~243 MB
__device__ __align__(256) __half g_fw0h[(size_t)H1 * NPAD];
__device__ __align__(256) __half g_h1  [(size_t)BATCH * H1];
__device__ __align__(256) __half g_fw1h[(size_t)H2 * H1];
__device__ __align__(256) __half g_h2  [(size_t)BATCH * H2];

// conv geometry tables
__constant__ int c_kh[7]  = {1, 2, 1, 3, 1, 4, 2};
__constant__ int c_kw[7]  = {2, 1, 3, 1, 4, 1, 2};
__constant__ int c_off[7] = {0, 768, 1536, 2048, 2560, 2816, 3072};

// ---------------- prep kernels ----------------
__global__ void k_cvt(const float* __restrict__ src, __half* __restrict__ dst, int n) {
    int i = blockIdx.x * blockDim.x + threadIdx.x;
    if (i < n) dst[i] = __float2half_rn(src[i]);
}

__global__ void k_cvt_pad(const float* __restrict__ src, __half* __restrict__ dst,
                          int rows, int cols, int colspad) {
    int i = blockIdx.x * blockDim.x + threadIdx.x;
    if (i >= rows * colspad) return;
    int r = i / colspad, c = i % colspad;
    dst[i] = (c < cols) ? __float2half_rn(src[r * cols + c]) : __half(0.0f);
}

__global__ void k_zero_w() {
    int i = blockIdx.x * blockDim.x + threadIdx.x;
    int n = NPAD * KIN;
    if (i < n) g_Wbig[i] = __half(0.0f);
    if (i < NPAD) g_bbig[i] = 0.0f;
}

struct ConvPtrs { const float* w[7]; const float* b[7]; };

__global__ void k_scatter(ConvPtrs cp) {
    int f = blockIdx.x * blockDim.x + threadIdx.x;
    if (f >= NC) return;
    int ci = 0;
#pragma unroll
    for (int t = 1; t < 7; t++) if (f >= c_off[t]) ci = t;
    int kh = c_kh[ci], kw = c_kw[ci];
    int oh = 4 - kh + 1, ow = 4 - kw + 1;
    int loc = f - c_off[ci];
    int o = loc / (oh * ow);
    int p = loc % (oh * ow);
    int y = p / ow, x = p % ow;
    const float* w = cp.w[ci];
    g_bbig[f] = cp.b[ci][o];
    for (int c = 0; c < 16; c++)
        for (int dy = 0; dy < kh; dy++)
            for (int dx = 0; dx < kw; dx++) {
                int k = c * 16 + (y + dy) * 4 + (x + dx);
                float wv = w[((o * 16 + c) * kh + dy) * kw + dx];
                g_Wbig[(size_t)f * KIN + k] = __float2half_rn(wv);
            }
}

// ---------------- GEMM (NT): C[M,N] = act(A[M,K] * B[N,K]^T + bias) ----------------
__device__ __forceinline__ uint32_t swz(uint32_t x) { return x ^ ((x >> 3) & 0x70); }

__device__ __forceinline__ void cp16(uint32_t saddr, const void* g) {
    asm volatile("cp.async.cg.shared.global [%0], [%1], 16;\n" :: "r"(saddr), "l"(g) : "memory");
}
__device__ __forceinline__ void cp_commit() {
    asm volatile("cp.async.commit_group;\n" ::: "memory");
}

__device__ __forceinline__ void ldsm4(uint32_t& r0, uint32_t& r1, uint32_t& r2, uint32_t& r3,
                                      uint32_t addr) {
    asm volatile("ldmatrix.sync.aligned.m8n8.x4.shared.b16 {%0,%1,%2,%3}, [%4];"
                 : "=r"(r0), "=r"(r1), "=r"(r2), "=r"(r3) : "r"(addr));
}

__device__ __forceinline__ void mma16816(float c[4], const uint32_t a[4], const uint32_t b[2]) {
    asm volatile(
        "mma.sync.aligned.m16n8k16.row.col.f32.f16.f16.f32 "
        "{%0,%1,%2,%3}, {%4,%5,%6,%7}, {%8,%9}, {%0,%1,%2,%3};"
        : "+f"(c[0]), "+f"(c[1]), "+f"(c[2]), "+f"(c[3])
        : "r"(a[0]), "r"(a[1]), "r"(a[2]), "r"(a[3]), "r"(b[0]), "r"(b[1]));
}

__device__ __forceinline__ void load_tiles(uint32_t sA, uint32_t sB,
                                           const __half* __restrict__ Ab,
                                           const __half* __restrict__ Bb,
                                           int K, int k0, int tid) {
#pragma unroll
    for (int p = 0; p < 4; p++) {
        int chunk = tid + p * 256;         // 0..1023
        int row = chunk >> 3;              // 0..127
        int cc  = chunk & 7;               // 0..7 (16B chunks within 128B row)
        uint32_t so = swz((uint32_t)(row * 128 + cc * 16));
        cp16(sA + so, Ab + (size_t)row * K + k0 + cc * 8);
        cp16(sB + so, Bb + (size_t)row * K + k0 + cc * 8);
    }
}

template <bool RELU>
__global__ void __launch_bounds__(256, 2)
gemm_nt(const __half* __restrict__ A, const __half* __restrict__ Bw,
        const float* __restrict__ bias, __half* __restrict__ C, int N, int K) {
    extern __shared__ char smemraw[];
    const int tid  = threadIdx.x;
    const int lane = tid & 31;
    const int w    = tid >> 5;
    const int wm   = w & 1;        // 2 warps along M (64 rows each)
    const int wn   = w >> 1;       // 4 warps along N (32 cols each)
    const int bm   = blockIdx.y, bn = blockIdx.x;

    uint32_t sbase = (uint32_t)__cvta_generic_to_shared(smemraw);
    // stage layout: [A0 16K][B0 16K][A1 16K][B1 16K]
    const __half* Ab = A  + (size_t)bm * 128 * K;
    const __half* Bb = Bw + (size_t)bn * 128 * K;

    float acc[4][4][4];
#pragma unroll
    for (int i = 0; i < 4; i++)
#pragma unroll
        for (int j = 0; j < 4; j++)
#pragma unroll
            for (int q = 0; q < 4; q++) acc[i][j][q] = 0.0f;

    const int nk = K >> 6;
    load_tiles(sbase, sbase + 16384, Ab, Bb, K, 0, tid);
    cp_commit();

#pragma unroll 1
    for (int kt = 0; kt < nk; ++kt) {
        uint32_t cs = (kt & 1) ? sbase + 32768 : sbase;
        if (kt + 1 < nk) {
            uint32_t ns = (kt & 1) ? sbase : sbase + 32768;
            load_tiles(ns, ns + 16384, Ab, Bb, K, (kt + 1) << 6, tid);
            cp_commit();
            asm volatile("cp.async.wait_group 1;\n" ::: "memory");
        } else {
            asm volatile("cp.async.wait_group 0;\n" ::: "memory");
        }
        __syncthreads();

        uint32_t aT = cs, bT = cs + 16384;
#pragma unroll
        for (int ks = 0; ks < 4; ++ks) {
            uint32_t af[4][4];
#pragma unroll
            for (int mt = 0; mt < 4; ++mt) {
                uint32_t off = swz((uint32_t)((wm * 64 + mt * 16 + (lane & 15)) * 128 +
                                              ks * 32 + ((lane >> 4) << 4)));
                ldsm4(af[mt][0], af[mt][1], af[mt][2], af[mt][3], aT + off);
            }
            uint32_t bf[4][2];
#pragma unroll
            for (int nt2 = 0; nt2 < 2; ++nt2) {
                int brow = wn * 32 + nt2 * 16 + ((lane & 16) >> 1) + (lane & 7);
                uint32_t off = swz((uint32_t)(brow * 128 + ks * 32 + (((lane >> 3) & 1) << 4)));
                uint32_t r0, r1, r2, r3;
                ldsm4(r0, r1, r2, r3, bT + off);
                bf[nt2 * 2][0] = r0;     bf[nt2 * 2][1] = r1;
                bf[nt2 * 2 + 1][0] = r2; bf[nt2 * 2 + 1][1] = r3;
            }
#pragma unroll
            for (int mt = 0; mt < 4; ++mt)
#pragma unroll
                for (int nt = 0; nt < 4; ++nt) mma16816(acc[mt][nt], af[mt], bf[nt]);
        }
        __syncthreads();
    }

    // epilogue: bias + optional relu, store fp16
#pragma unroll
    for (int mt = 0; mt < 4; ++mt) {
        int r0 = bm * 128 + wm * 64 + mt * 16 + (lane >> 2);
#pragma unroll
        for (int nt = 0; nt < 4; ++nt) {
            int col = bn * 128 + wn * 32 + nt * 8 + ((lane & 3) << 1);
            float2 bb = *(const float2*)(bias + col);
            float v0 = acc[mt][nt][0] + bb.x;
            float v1 = acc[mt][nt][1] + bb.y;
            float v2 = acc[mt][nt][2] + bb.x;
            float v3 = acc[mt][nt][3] + bb.y;
            if (RELU) {
                v0 = fmaxf(v0, 0.0f); v1 = fmaxf(v1, 0.0f);
                v2 = fmaxf(v2, 0.0f); v3 = fmaxf(v3, 0.0f);
            }
            *(__half2*)(C + (size_t)r0 * N + col)       = __floats2half2_rn(v0, v1);
            *(__half2*)(C + (size_t)(r0 + 8) * N + col) = __floats2half2_rn(v2, v3);
        }
    }
}

// ---------------- tiny final FC (fp32) ----------------
__global__ void k_fc3(const __half* __restrict__ h2, const float* __restrict__ fw2,
                      const float* __restrict__ fb2, float* __restrict__ out) {
    int idx = blockIdx.x * blockDim.x + threadIdx.x;   // b*4 + j over 131072
    if (idx >= BATCH * NA) return;
    int b = idx >> 2, j = idx & 3;
    const __half2* hr = (const __half2*)(h2 + (size_t)b * H2);
    const float* wr = fw2 + j * H2;
    float acc = fb2[j];
#pragma unroll
    for (int k = 0; k < H2 / 2; k++) {
        float2 hf = __half22float2(hr[k]);
        acc += hf.x * wr[2 * k] + hf.y * wr[2 * k + 1];
    }
    out[idx] = acc;
}

// ---------------- launch ----------------
extern "C" void kernel_launch(void* const* d_in, const int* in_sizes, int n_in,
                              void* d_out, int out_size) {
    const float* x = (const float*)d_in[0];
    ConvPtrs cp;
    for (int i = 0; i < 7; i++) {
        cp.w[i] = (const float*)d_in[1 + 2 * i];
        cp.b[i] = (const float*)d_in[2 + 2 * i];
    }
    const float* fw0 = (const float*)d_in[15];
    const float* fb0 = (const float*)d_in[16];
    const float* fw1 = (const float*)d_in[17];
    const float* fb1 = (const float*)d_in[18];
    const float* fw2 = (const float*)d_in[19];
    const float* fb2 = (const float*)d_in[20];
    float* out = (float*)d_out;

    cudaFuncSetAttribute(gemm_nt<true>, cudaFuncAttributeMaxDynamicSharedMemorySize, 65536);

    __half *Xh, *Wbig, *comb, *fw0h, *h1, *fw1h, *h2;
    float* bbig;
    cudaGetSymbolAddress((void**)&Xh,   g_Xh);
    cudaGetSymbolAddress((void**)&Wbig, g_Wbig);
    cudaGetSymbolAddress((void**)&bbig, g_bbig);
    cudaGetSymbolAddress((void**)&comb, g_comb);
    cudaGetSymbolAddress((void**)&fw0h, g_fw0h);
    cudaGetSymbolAddress((void**)&h1,   g_h1);
    cudaGetSymbolAddress((void**)&fw1h, g_fw1h);
    cudaGetSymbolAddress((void**)&h2,   g_h2);

    // prep
    {
        int n = BATCH * KIN;
        k_cvt<<<(n + 255) / 256, 256>>>(x, Xh, n);
    }
    {
        int n = NPAD * KIN;
        k_zero_w<<<(n + 255) / 256, 256>>>();
        k_scatter<<<(NC + 255) / 256, 256>>>(cp);
    }
    {
        int n = H1 * NPAD;
        k_cvt_pad<<<(n + 255) / 256, 256>>>(fw0, fw0h, H1, NC, NPAD);
        int n2 = H2 * H1;
        k_cvt<<<(n2 + 255) / 256, 256>>>(fw1, fw1h, n2);
    }

    // GEMM1: combined = relu(Xh * Wbig^T + bbig)   [32768, 3712], K=256
    {
        dim3 grid(NPAD / 128, BATCH / 128);
        gemm_nt<true><<<grid, 256, 65536>>>(Xh, Wbig, bbig, comb, NPAD, KIN);
    }
    // GEMM2: h1 = relu(combined * fw0h^T + fb0)    [32768, 512], K=3712
    {
        dim3 grid(H1 / 128, BATCH / 128);
        gemm_nt<true><<<grid, 256, 65536>>>(comb, fw0h, fb0, h1, H1, NPAD);
    }
    // GEMM3: h2 = relu(h1 * fw1h^T + fb1)          [32768, 128], K=512
    {
        dim3 grid(H2 / 128, BATCH / 128);
        gemm_nt<true><<<grid, 256, 65536>>>(h1, fw1h, fb1, h2, H2, H1);
    }
    // final: out = h2 * fw2^T + fb2                [32768, 4] fp32
    {
        int n = BATCH * NA;
        k_fc3<<<(n + 255) / 256, 256>>>(h2, fw2, fb2, out);
    }
}